// round 17
// baseline (speedup 1.0000x reference)
#include <cuda_runtime.h>
#include <cuda_fp16.h>
#include <stdint.h>
#include <math.h>

#define MAXN 20000
#define MAXE 320000

// ---- scratch (static device globals; referenced ONLY from device code) ----
__device__ float  g_x[4][MAXN * 64];   // x_all slices: h, out1, out2, out3 (fp32)
__device__ __half g_qh[MAXN * 64];     // q (layers 2,3) / layer-1 v (flat)
// interleaved k/v: [node][slice][pair(32)] -> uint2 {k2p,k2p+1 | v2p,v2p+1} (fp16)
__device__ uint2  g_kv [MAXN * 96];    // layer t=2 (slices 0,1)
__device__ uint2  g_kv2[MAXN * 96];    // layer t=3 (slices 0,1,2)
__device__ int    g_cnt[MAXN];
__device__ int    g_cur[MAXN];
__device__ int    g_off[MAXN + 1];
__device__ float  g_dinv[MAXN];
__device__ int    g_src[MAXE];

struct Jobs5 { int4 j[5]; };   // {kind(0q,1k,2v,3v-flat), layer, in_slice, buf*4+slice}

__device__ __forceinline__ float to_tf32(float x) {
    uint32_t u;
    asm("cvt.rna.tf32.f32 %0, %1;" : "=r"(u) : "f"(x));
    return __uint_as_float(u);
}

__device__ __forceinline__ void mma_tf32(float& d0, float& d1, float& d2, float& d3,
                                         uint32_t a0, uint32_t a1, uint32_t a2, uint32_t a3,
                                         uint32_t b0, uint32_t b1) {
    asm("mma.sync.aligned.m16n8k8.row.col.f32.tf32.tf32.f32 "
        "{%0,%1,%2,%3}, {%4,%5,%6,%7}, {%8,%9}, {%0,%1,%2,%3};"
        : "+f"(d0), "+f"(d1), "+f"(d2), "+f"(d3)
        : "r"(a0), "r"(a1), "r"(a2), "r"(a3), "r"(b0), "r"(b1));
}

// ---------------- 64x64 tf32 GEMM job (shared body) ----------------
__device__ __forceinline__ void gemm_job(const float* __restrict__ W, const float* __restrict__ B,
                                         const float* __restrict__ in, __half* out,
                                         int ostride, int kvsel, int base, int n) {
    __shared__ float xs[64][68];
    __shared__ float ws[64][68];
    int tid = threadIdx.x;
    int warp = tid >> 5, lane = tid & 31;

    for (int i = tid; i < 64 * 16; i += 256) {
        int r = i >> 4, c4 = (i & 15) * 4;
        int node = base + r;
        float4 vv = (node < n) ? ((const float4*)(in + (size_t)node * 64))[i & 15]
                               : make_float4(0.f, 0.f, 0.f, 0.f);
        xs[r][c4]     = to_tf32(vv.x);
        xs[r][c4 + 1] = to_tf32(vv.y);
        xs[r][c4 + 2] = to_tf32(vv.z);
        xs[r][c4 + 3] = to_tf32(vv.w);
    }
    for (int i = tid; i < 64 * 16; i += 256) {
        int r = i >> 4, c4 = (i & 15) * 4;
        float4 wv = ((const float4*)(W + (size_t)r * 64))[i & 15];
        ws[r][c4]     = to_tf32(wv.x);
        ws[r][c4 + 1] = to_tf32(wv.y);
        ws[r][c4 + 2] = to_tf32(wv.z);
        ws[r][c4 + 3] = to_tf32(wv.w);
    }
    __syncthreads();

    int r0 = (warp & 3) * 16;
    int c0 = (warp >> 2) * 32;
    float acc[4][4] = {};
    #pragma unroll
    for (int ks = 0; ks < 64; ks += 8) {
        uint32_t a0 = __float_as_uint(xs[r0 + (lane >> 2)][ks + (lane & 3)]);
        uint32_t a1 = __float_as_uint(xs[r0 + (lane >> 2) + 8][ks + (lane & 3)]);
        uint32_t a2 = __float_as_uint(xs[r0 + (lane >> 2)][ks + (lane & 3) + 4]);
        uint32_t a3 = __float_as_uint(xs[r0 + (lane >> 2) + 8][ks + (lane & 3) + 4]);
        #pragma unroll
        for (int nt = 0; nt < 4; nt++) {
            int nc = c0 + nt * 8;
            uint32_t b0 = __float_as_uint(ws[ks + (lane & 3)][nc + (lane >> 2)]);
            uint32_t b1 = __float_as_uint(ws[ks + (lane & 3) + 4][nc + (lane >> 2)]);
            mma_tf32(acc[nt][0], acc[nt][1], acc[nt][2], acc[nt][3], a0, a1, a2, a3, b0, b1);
        }
    }
    int rA = r0 + (lane >> 2), rB = rA + 8;
    #pragma unroll
    for (int nt = 0; nt < 4; nt++) {
        int c = c0 + nt * 8 + (lane & 3) * 2;    // even
        float bx = B[c], by = B[c + 1];
        int coff = (kvsel < 0) ? c : ((c >> 1) << 2) + kvsel;
        int nodeA = base + rA;
        if (nodeA < n)
            *(__half2*)(out + (size_t)nodeA * ostride + coff) =
                __floats2half2_rn(acc[nt][0] + bx, acc[nt][1] + by);
        int nodeB = base + rB;
        if (nodeB < n)
            *(__half2*)(out + (size_t)nodeB * ostride + coff) =
                __floats2half2_rn(acc[nt][2] + bx, acc[nt][3] + by);
    }
}

__device__ __forceinline__ void run_job(int4 J,
        const float* wq, const float* bq, const float* wk, const float* bk,
        const float* wv, const float* bv, int base, int n) {
    int kind = J.x, layer = J.y;
    const float* W = (kind == 0) ? wq : (kind == 1) ? wk : wv;
    const float* B = (kind == 0) ? bq : (kind == 1) ? bk : bv;
    W += layer * 4096; B += layer * 64;
    const float* in = g_x[J.z];
    __half* out; int ostride, kvsel;
    if (kind == 0 || kind == 3) { out = g_qh; ostride = 64; kvsel = -1; }
    else {
        int buf = J.w >> 2, s = J.w & 3;
        out = (__half*)(buf ? g_kv2 : g_kv) + s * 128;
        ostride = 384; kvsel = (kind == 1) ? 0 : 2;
    }
    gemm_job(W, B, in, out, ostride, kvsel, base, n);
}

// ---------------- lin1 body (256->64, tf32 mma), writes g_x[0] ----------------
__device__ __forceinline__ void lin1_job(const float* __restrict__ x, const float* __restrict__ W,
                                         const float* __restrict__ b, int n, int base) {
    __shared__ float xs1[64][68];
    __shared__ float ws1[64][68];
    int tid = threadIdx.x;
    int warp = tid >> 5, lane = tid & 31;
    int r0 = (warp & 3) * 16;
    int c0 = (warp >> 2) * 32;
    float acc[4][4] = {};

    for (int kc = 0; kc < 4; kc++) {
        for (int i = tid; i < 64 * 16; i += 256) {
            int r = i >> 4, c4 = (i & 15) * 4;
            int node = base + r;
            float4 vv = (node < n) ? ((const float4*)(x + (size_t)node * 256 + kc * 64))[i & 15]
                                   : make_float4(0.f, 0.f, 0.f, 0.f);
            xs1[r][c4]     = to_tf32(vv.x);
            xs1[r][c4 + 1] = to_tf32(vv.y);
            xs1[r][c4 + 2] = to_tf32(vv.z);
            xs1[r][c4 + 3] = to_tf32(vv.w);
        }
        for (int i = tid; i < 64 * 16; i += 256) {
            int r = i >> 4, c4 = (i & 15) * 4;
            float4 wv = ((const float4*)(W + (size_t)(kc * 64 + r) * 64))[i & 15];
            ws1[r][c4]     = to_tf32(wv.x);
            ws1[r][c4 + 1] = to_tf32(wv.y);
            ws1[r][c4 + 2] = to_tf32(wv.z);
            ws1[r][c4 + 3] = to_tf32(wv.w);
        }
        __syncthreads();
        #pragma unroll
        for (int ks = 0; ks < 64; ks += 8) {
            uint32_t a0 = __float_as_uint(xs1[r0 + (lane >> 2)][ks + (lane & 3)]);
            uint32_t a1 = __float_as_uint(xs1[r0 + (lane >> 2) + 8][ks + (lane & 3)]);
            uint32_t a2 = __float_as_uint(xs1[r0 + (lane >> 2)][ks + (lane & 3) + 4]);
            uint32_t a3 = __float_as_uint(xs1[r0 + (lane >> 2) + 8][ks + (lane & 3) + 4]);
            #pragma unroll
            for (int nt = 0; nt < 4; nt++) {
                int nc = c0 + nt * 8;
                uint32_t b0 = __float_as_uint(ws1[ks + (lane & 3)][nc + (lane >> 2)]);
                uint32_t b1 = __float_as_uint(ws1[ks + (lane & 3) + 4][nc + (lane >> 2)]);
                mma_tf32(acc[nt][0], acc[nt][1], acc[nt][2], acc[nt][3], a0, a1, a2, a3, b0, b1);
            }
        }
        __syncthreads();
    }
    int rA = r0 + (lane >> 2), rB = rA + 8;
    #pragma unroll
    for (int nt = 0; nt < 4; nt++) {
        int c = c0 + nt * 8 + (lane & 3) * 2;
        float bx = b[c], by = b[c + 1];
        int nodeA = base + rA;
        if (nodeA < n) {
            float2 o = make_float2(fmaxf(acc[nt][0] + bx, 0.f), fmaxf(acc[nt][1] + by, 0.f));
            *(float2*)(g_x[0] + (size_t)nodeA * 64 + c) = o;
        }
        int nodeB = base + rB;
        if (nodeB < n) {
            float2 o = make_float2(fmaxf(acc[nt][2] + bx, 0.f), fmaxf(acc[nt][3] + by, 0.f));
            *(float2*)(g_x[0] + (size_t)nodeB * 64 + c) = o;
        }
    }
}

// ---------------- fused launches ----------------
// L1: zero g_cnt (blocks [0,zb)) U lin1 (blocks [zb, zb+gB64))
__global__ void k_zero_lin1(const float* __restrict__ x, const float* __restrict__ W,
                            const float* __restrict__ b, int n, int zb) {
    if ((int)blockIdx.x < zb) {
        int i = blockIdx.x * 256 + threadIdx.x;
        if (i < n) g_cnt[i] = 0;
    } else {
        lin1_job(x, W, b, n, ((int)blockIdx.x - zb) * 64);
    }
}

// L2: degree histogram U layer-1 V projection (flat into g_qh)
__global__ void k_hist_v1(const int* __restrict__ ei, int E,
                          const float* __restrict__ wv, const float* __restrict__ bv,
                          int n, int hb) {
    if ((int)blockIdx.x < hb) {
        int e = blockIdx.x * 256 + threadIdx.x;
        if (e < E) atomicAdd(&g_cnt[ei[E + e]], 1);
    } else {
        gemm_job(wv, bv, g_x[0], g_qh, 64, -1, ((int)blockIdx.x - hb) * 64, n);
    }
}

// L3: single-block scan (block 0) U 4 slice-0 K/V GEMM jobs
__global__ void k_scan_jobs(Jobs5 jb,
                            const float* wq, const float* bq, const float* wk, const float* bk,
                            const float* wv, const float* bv, int n, int gB64) {
    if (blockIdx.x == 0) {
        __shared__ int ssum[256];
        int tid = threadIdx.x;
        int chunk = (n + 255) >> 8;
        int beg = tid * chunk;
        int end = min(beg + chunk, n);
        int s = 0;
        for (int i = beg; i < end; i++) s += g_cnt[i];
        ssum[tid] = s;
        __syncthreads();
        for (int d = 1; d < 256; d <<= 1) {
            int v = (tid >= d) ? ssum[tid - d] : 0;
            __syncthreads();
            ssum[tid] += v;
            __syncthreads();
        }
        int run = ssum[tid] - s;
        for (int i = beg; i < end; i++) {
            g_off[i] = run;
            g_cur[i] = run;
            g_dinv[i] = rsqrtf((float)(g_cnt[i] + 1));
            run += g_cnt[i];
        }
        if (tid == 255) g_off[n] = ssum[255];
    } else {
        int bI = (int)blockIdx.x - 1;
        int job = bI / gB64;
        run_job(jb.j[job], wq, bq, wk, bk, wv, bv, (bI % gB64) * 64, n);
    }
}

// generic multi-job GEMM launch: grid (gB64, njobs)
__global__ void k_jobs(Jobs5 jb,
                       const float* wq, const float* bq, const float* wk, const float* bk,
                       const float* wv, const float* bv, int n) {
    run_job(jb.j[blockIdx.y], wq, bq, wk, bk, wv, bv, blockIdx.x * 64, n);
}

__global__ void k_scatter(const int* __restrict__ ei, int E) {
    int e = blockIdx.x * blockDim.x + threadIdx.x;
    if (e < E) {
        int dst = ei[E + e];
        int p = atomicAdd(&g_cur[dst], 1);
        g_src[p] = ei[e];
    }
}

// -------- layer-1 aggregation: attn==1; v flat in g_qh --------
__global__ void k_gather1(int n) {
    int gw = (blockIdx.x * blockDim.x + threadIdx.x) >> 5;
    int lane = threadIdx.x & 31;
    if (gw >= n) return;
    int dst = gw;
    float did = g_dinv[dst];
    int e0 = g_off[dst], e1 = g_off[dst + 1];
    int tot = e1 - e0 + 1;
    float2 acc = make_float2(0.f, 0.f);
    for (int base = 0; base < tot; base += 32) {
        int idx = e0 + base + lane;
        int mysrc = (idx < e1) ? g_src[idx] : dst;
        float mydinv = g_dinv[mysrc];
        int cnt = min(32, tot - base);
        for (int j = 0; j < cnt; j++) {
            int src = __shfl_sync(0xffffffffu, mysrc, j);
            float sdi = __shfl_sync(0xffffffffu, mydinv, j);
            float2 v2 = __half22float2(((const __half2*)(g_qh + (size_t)src * 64))[lane]);
            acc.x += v2.x * sdi;
            acc.y += v2.y * sdi;
        }
    }
    float2 o;
    o.x = fmaxf(acc.x * did, 0.f);
    o.y = fmaxf(acc.y * did, 0.f);
    ((float2*)(g_x[1] + (size_t)dst * 64))[lane] = o;
}

// -------- edge attention + aggregation (T>=2) --------
template <int T>
__global__ void k_gather(int n) {
    int gw = (blockIdx.x * blockDim.x + threadIdx.x) >> 5;
    int lane = threadIdx.x & 31;
    if (gw >= n) return;
    int dst = gw;
    const uint2* kvarr = (T == 3) ? g_kv2 : g_kv;
    const float inv_sqrt_d = 0.3535533905932738f;
    float2 q2 = __half22float2(((const __half2*)(g_qh + (size_t)dst * 64))[lane]);
    float did = g_dinv[dst];
    int e0 = g_off[dst], e1 = g_off[dst + 1];
    int tot = e1 - e0 + 1;
    float2 acc = make_float2(0.f, 0.f);
    for (int base = 0; base < tot; base += 32) {
        int idx = e0 + base + lane;
        int mysrc = (idx < e1) ? g_src[idx] : dst;
        float mydinv = g_dinv[mysrc];
        int cnt = min(32, tot - base);
        uint2 u[T];
        {
            int s0 = __shfl_sync(0xffffffffu, mysrc, 0);
            const uint2* kvp = kvarr + (size_t)s0 * 96 + lane;
            #pragma unroll
            for (int s = 0; s < T; s++) u[s] = kvp[s * 32];
        }
        for (int j = 0; j < cnt; j++) {
            uint2 nx[T];
            if (j + 1 < cnt) {
                int s1 = __shfl_sync(0xffffffffu, mysrc, j + 1);
                const uint2* kvp = kvarr + (size_t)s1 * 96 + lane;
                #pragma unroll
                for (int s = 0; s < T; s++) nx[s] = kvp[s * 32];
            }
            float sdi = __shfl_sync(0xffffffffu, mydinv, j);
            float sc[T];
            float sum = 0.f;
            #pragma unroll
            for (int s = 0; s < T; s++) {
                float2 kk = __half22float2(*(const __half2*)&u[s].x);
                float p = q2.x * kk.x + q2.y * kk.y;
                p += __shfl_xor_sync(0xffffffffu, p, 1);
                p += __shfl_xor_sync(0xffffffffu, p, 2);
                sc[s] = __expf(p * inv_sqrt_d);
                sum += sc[s];
            }
            float scale = __fdividef(sdi, sum);
            float2 m = make_float2(0.f, 0.f);
            #pragma unroll
            for (int s = 0; s < T; s++) {
                float2 vv = __half22float2(*(const __half2*)&u[s].y);
                m.x += sc[s] * vv.x;
                m.y += sc[s] * vv.y;
            }
            acc.x += m.x * scale;
            acc.y += m.y * scale;
            #pragma unroll
            for (int s = 0; s < T; s++) u[s] = nx[s];
        }
    }
    float2 o;
    o.x = fmaxf(acc.x * did, 0.f);
    o.y = fmaxf(acc.y * did, 0.f);
    ((float2*)(g_x[T] + (size_t)dst * 64))[lane] = o;
}

// ---------------- lin2 + log_softmax ----------------
__global__ void k_lin2_ls(const float* __restrict__ W, const float* __restrict__ b,
                          float* __restrict__ out, int n) {
    int gw = (blockIdx.x * blockDim.x + threadIdx.x) >> 5;
    int lane = threadIdx.x & 31;
    if (gw >= n) return;
    const float* hr = g_x[3] + (size_t)gw * 64;
    float2 acc = ((const float2*)b)[lane];
    #pragma unroll 8
    for (int k = 0; k < 64; k++) {
        float hk = hr[k];
        float2 w2 = ((const float2*)(W + k * 64))[lane];
        acc.x += hk * w2.x;
        acc.y += hk * w2.y;
    }
    float m = fmaxf(acc.x, acc.y);
    #pragma unroll
    for (int o = 16; o > 0; o >>= 1) m = fmaxf(m, __shfl_xor_sync(0xffffffffu, m, o));
    float se = __expf(acc.x - m) + __expf(acc.y - m);
    #pragma unroll
    for (int o = 16; o > 0; o >>= 1) se += __shfl_xor_sync(0xffffffffu, se, o);
    float lse = m + logf(se);
    float2 r;
    r.x = acc.x - lse;
    r.y = acc.y - lse;
    ((float2*)(out + (size_t)gw * 64))[lane] = r;
}

// ---------------- host launcher (kernel launches ONLY) ----------------
extern "C" void kernel_launch(void* const* d_in, const int* in_sizes, int n_in,
                              void* d_out, int out_size) {
    const float* x  = (const float*)d_in[0];
    const int*   ei = (const int*)d_in[1];     // int32 (JAX default int without x64)
    const float* w1 = (const float*)d_in[2];
    const float* b1 = (const float*)d_in[3];
    const float* wq = (const float*)d_in[4];
    const float* bq = (const float*)d_in[5];
    const float* wk = (const float*)d_in[6];
    const float* bk = (const float*)d_in[7];
    const float* wv = (const float*)d_in[8];
    const float* bv = (const float*)d_in[9];
    const float* w2 = (const float*)d_in[10];
    const float* b2 = (const float*)d_in[11];

    int n = in_sizes[0] / 256;   // IN_C = 256
    int E = in_sizes[1] / 2;

    int zb = (n + 255) / 256;
    int hb = (E + 255) / 256;
    int gB64 = (n + 63) / 64;
    int gWarp = (n * 32 + 255) / 256;

    // L1: zero cnt U lin1
    k_zero_lin1<<<zb + gB64, 256>>>(x, w1, b1, n, zb);
    // L2: hist U layer-1 V (flat -> g_qh)
    k_hist_v1<<<hb + gB64, 256>>>(ei, E, wv, bv, n, hb);
    // L3: scan U slice-0 K/V for layers 2 (buf0) and 3 (buf1)
    Jobs5 j3;
    j3.j[0] = make_int4(1, 1, 0, 0);   // K  layer1 in0 -> kv  s0
    j3.j[1] = make_int4(2, 1, 0, 0);   // V  layer1 in0 -> kv  s0
    j3.j[2] = make_int4(1, 2, 0, 4);   // K  layer2 in0 -> kv2 s0
    j3.j[3] = make_int4(2, 2, 0, 4);   // V  layer2 in0 -> kv2 s0
    j3.j[4] = make_int4(0, 0, 0, 0);
    k_scan_jobs<<<1 + 4 * gB64, 256>>>(j3, wq, bq, wk, bk, wv, bv, n, gB64);
    // L4: scatter
    k_scatter<<<hb, 256>>>(ei, E);
    // L5: layer-1 aggregation
    k_gather1<<<gWarp, 256>>>(n);
    // L6: layer-2 Q + slice-1 K/V (layers 2 and 3)
    Jobs5 j6;
    j6.j[0] = make_int4(0, 1, 1, 0);   // Q  layer1 in1 -> g_qh
    j6.j[1] = make_int4(1, 1, 1, 1);   // K  layer1 in1 -> kv  s1
    j6.j[2] = make_int4(2, 1, 1, 1);   // V  layer1 in1 -> kv  s1
    j6.j[3] = make_int4(1, 2, 1, 5);   // K  layer2 in1 -> kv2 s1
    j6.j[4] = make_int4(2, 2, 1, 5);   // V  layer2 in1 -> kv2 s1
    k_jobs<<<dim3(gB64, 5), 256>>>(j6, wq, bq, wk, bk, wv, bv, n);
    // L7: layer-2 aggregation
    k_gather<2><<<gWarp, 256>>>(n);
    // L8: layer-3 Q + slice-2 K/V
    Jobs5 j8;
    j8.j[0] = make_int4(0, 2, 2, 0);   // Q  layer2 in2 -> g_qh
    j8.j[1] = make_int4(1, 2, 2, 6);   // K  layer2 in2 -> kv2 s2
    j8.j[2] = make_int4(2, 2, 2, 6);   // V  layer2 in2 -> kv2 s2
    j8.j[3] = make_int4(0, 0, 0, 0);
    j8.j[4] = make_int4(0, 0, 0, 0);
    k_jobs<<<dim3(gB64, 3), 256>>>(j8, wq, bq, wk, bk, wv, bv, n);
    // L9: layer-3 aggregation
    k_gather<3><<<gWarp, 256>>>(n);
    // L10: output head
    k_lin2_ls<<<gWarp, 256>>>(w2, b2, (float*)d_out, n);
}